// round 1
// baseline (speedup 1.0000x reference)
#include <cuda_runtime.h>
#include <cuda_bf16.h>
#include <math.h>

// Problem constants
#define TOK   8192        // B*S = 4*2048
#define HDIM  1024
#define NEXP  8
#define FDIM  4096        // 4*H
#define NSLOT (TOK*2)     // 16384 token-expert assignments

// GEMM tiling
#define BM 128
#define BN 128
#define BK 16
#define NTHREADS 256

// ---------------- device scratch (no cudaMalloc allowed) ----------------
__device__ int   g_count[NEXP];
__device__ int   g_cursor[NEXP];
__device__ int   g_offset[NEXP];
__device__ int   g_exp[TOK * 2];
__device__ float g_wt[TOK * 2];
__device__ int   g_tok_slot[NSLOT];
__device__ float g_wt_slot[NSLOT];
__device__ float g_hmid[(size_t)NSLOT * FDIM];   // 256 MB scratch

// ---------------- small kernels ----------------
__global__ void zero_counts_kernel() {
    int i = threadIdx.x;
    if (i < NEXP) g_count[i] = 0;
}

// One warp per token: logits over 8 experts, top-2, renormalized weights.
__global__ void router_kernel(const float* __restrict__ x,
                              const float* __restrict__ rw,
                              const float* __restrict__ rb) {
    int t = blockIdx.x * 8 + threadIdx.y;      // 8 warps per block
    if (t >= TOK) return;
    int lane = threadIdx.x;

    float acc[8];
#pragma unroll
    for (int e = 0; e < 8; e++) acc[e] = 0.f;

    const float* xr = x + (size_t)t * HDIM;
    for (int h = lane; h < HDIM; h += 32) {
        float xv = xr[h];
        const float4 w0 = *(const float4*)(rw + h * 8);
        const float4 w1 = *(const float4*)(rw + h * 8 + 4);
        acc[0] += xv * w0.x; acc[1] += xv * w0.y;
        acc[2] += xv * w0.z; acc[3] += xv * w0.w;
        acc[4] += xv * w1.x; acc[5] += xv * w1.y;
        acc[6] += xv * w1.z; acc[7] += xv * w1.w;
    }
#pragma unroll
    for (int off = 16; off > 0; off >>= 1) {
#pragma unroll
        for (int e = 0; e < 8; e++)
            acc[e] += __shfl_down_sync(0xffffffffu, acc[e], off);
    }
    if (lane == 0) {
        float l[8];
#pragma unroll
        for (int e = 0; e < 8; e++) l[e] = acc[e] + rb[e];
        // softmax is monotone; top-2 indices from logits, probs via exp.
        float mx = l[0];
#pragma unroll
        for (int e = 1; e < 8; e++) mx = fmaxf(mx, l[e]);
        float p[8];
#pragma unroll
        for (int e = 0; e < 8; e++) p[e] = __expf(l[e] - mx);

        int e1 = 0; float p1 = p[0];
#pragma unroll
        for (int e = 1; e < 8; e++) if (p[e] > p1) { p1 = p[e]; e1 = e; }
        int e2 = -1; float p2 = -1.f;
#pragma unroll
        for (int e = 0; e < 8; e++) if (e != e1 && p[e] > p2) { p2 = p[e]; e2 = e; }

        float inv = 1.f / (p1 + p2);
        g_exp[t * 2 + 0] = e1; g_wt[t * 2 + 0] = p1 * inv;
        g_exp[t * 2 + 1] = e2; g_wt[t * 2 + 1] = p2 * inv;
        atomicAdd(&g_count[e1], 1);
        atomicAdd(&g_count[e2], 1);
    }
}

__global__ void prefix_kernel() {
    if (threadIdx.x == 0) {
        int o = 0;
        for (int e = 0; e < NEXP; e++) {
            g_offset[e] = o;
            o += g_count[e];
            g_cursor[e] = 0;
        }
    }
}

__global__ void scatter_kernel() {
    int t = blockIdx.x * blockDim.x + threadIdx.x;
    if (t >= TOK) return;
#pragma unroll
    for (int k = 0; k < 2; k++) {
        int e = g_exp[t * 2 + k];
        float w = g_wt[t * 2 + k];
        int pos = atomicAdd(&g_cursor[e], 1);
        int slot = g_offset[e] + pos;
        g_tok_slot[slot] = t;
        g_wt_slot[slot] = w;
    }
}

__device__ __forceinline__ float gelu_exact(float v) {
    return 0.5f * v * (1.0f + erff(v * 0.70710678118654752f));
}

// ---------------- GEMM1: hmid = gelu(gather(x) @ w1[e] + b1[e]) ----------------
// A: gathered x rows [cnt, 1024]; B: w1[e] [1024, 4096]; C: g_hmid segment
__global__ void __launch_bounds__(NTHREADS)
gemm1_kernel(const float* __restrict__ x,
             const float* __restrict__ w1,
             const float* __restrict__ b1) {
    const int e = blockIdx.z;
    const int cnt = g_count[e];
    const int m0 = blockIdx.y * BM;
    if (m0 >= cnt) return;
    const int n0 = blockIdx.x * BN;
    const int base = g_offset[e];
    const int* toks = g_tok_slot + base;
    const float* B = w1 + (size_t)e * HDIM * FDIM;
    float* Cseg = g_hmid + (size_t)base * FDIM;

    __shared__ float As[BK][BM];
    __shared__ float Bs[BK][BN];

    const int tid = threadIdx.x;
    const int tx = tid & 15;
    const int ty = tid >> 4;

    // A-load mapping: row = idx % 128, c4 = (idx/128)*4  (conflict-free smem stores)
    int a_row[2]; const float* a_ptr[2]; int a_c4[2]; bool a_ok[2];
#pragma unroll
    for (int i = 0; i < 2; i++) {
        int idx = tid + i * NTHREADS;
        a_row[i] = idx & 127;
        a_c4[i]  = (idx >> 7) * 4;
        int m = m0 + a_row[i];
        a_ok[i] = (m < cnt);
        a_ptr[i] = a_ok[i] ? (x + (size_t)toks[m] * HDIM + a_c4[i]) : x;
    }

    float acc[8][8];
#pragma unroll
    for (int i = 0; i < 8; i++)
#pragma unroll
        for (int j = 0; j < 8; j++) acc[i][j] = 0.f;

    for (int k0 = 0; k0 < HDIM; k0 += BK) {
#pragma unroll
        for (int i = 0; i < 2; i++) {
            float4 v = make_float4(0.f, 0.f, 0.f, 0.f);
            if (a_ok[i]) v = *(const float4*)(a_ptr[i] + k0);
            As[a_c4[i] + 0][a_row[i]] = v.x;
            As[a_c4[i] + 1][a_row[i]] = v.y;
            As[a_c4[i] + 2][a_row[i]] = v.z;
            As[a_c4[i] + 3][a_row[i]] = v.w;
        }
#pragma unroll
        for (int i = 0; i < 2; i++) {
            int idx = tid + i * NTHREADS;
            int row = idx >> 5;
            int c4 = (idx & 31) * 4;
            float4 v = *(const float4*)(B + (size_t)(k0 + row) * FDIM + n0 + c4);
            *(float4*)&Bs[row][c4] = v;
        }
        __syncthreads();
#pragma unroll
        for (int k = 0; k < BK; k++) {
            float a[8], b[8];
#pragma unroll
            for (int i = 0; i < 8; i++) a[i] = As[k][ty * 8 + i];
#pragma unroll
            for (int j = 0; j < 8; j++) b[j] = Bs[k][tx * 8 + j];
#pragma unroll
            for (int i = 0; i < 8; i++)
#pragma unroll
                for (int j = 0; j < 8; j++) acc[i][j] += a[i] * b[j];
        }
        __syncthreads();
    }

#pragma unroll
    for (int i = 0; i < 8; i++) {
        int m = m0 + ty * 8 + i;
        if (m >= cnt) break;
        float* crow = Cseg + (size_t)m * FDIM + n0;
#pragma unroll
        for (int j = 0; j < 8; j++) {
            int n = tx * 8 + j;
            float v = acc[i][j] + b1[e * FDIM + n0 + n];
            crow[n] = gelu_exact(v);
        }
    }
}

// ---------------- GEMM2: out[tok] += wt * (hmid @ w2[e] + b2[e]) ----------------
__global__ void __launch_bounds__(NTHREADS)
gemm2_kernel(const float* __restrict__ w2,
             const float* __restrict__ b2,
             float* __restrict__ out) {
    const int e = blockIdx.z;
    const int cnt = g_count[e];
    const int m0 = blockIdx.y * BM;
    if (m0 >= cnt) return;
    const int n0 = blockIdx.x * BN;
    const int base = g_offset[e];
    const float* Aseg = g_hmid + (size_t)base * FDIM;
    const float* B = w2 + (size_t)e * FDIM * HDIM;

    __shared__ float As[BK][BM];
    __shared__ float Bs[BK][BN];

    const int tid = threadIdx.x;
    const int tx = tid & 15;
    const int ty = tid >> 4;

    int a_row[2]; int a_c4[2]; bool a_ok[2];
#pragma unroll
    for (int i = 0; i < 2; i++) {
        int idx = tid + i * NTHREADS;
        a_row[i] = idx & 127;
        a_c4[i]  = (idx >> 7) * 4;
        a_ok[i] = (m0 + a_row[i] < cnt);
    }

    float acc[8][8];
#pragma unroll
    for (int i = 0; i < 8; i++)
#pragma unroll
        for (int j = 0; j < 8; j++) acc[i][j] = 0.f;

    for (int k0 = 0; k0 < FDIM; k0 += BK) {
#pragma unroll
        for (int i = 0; i < 2; i++) {
            float4 v = make_float4(0.f, 0.f, 0.f, 0.f);
            if (a_ok[i])
                v = *(const float4*)(Aseg + (size_t)(m0 + a_row[i]) * FDIM + k0 + a_c4[i]);
            As[a_c4[i] + 0][a_row[i]] = v.x;
            As[a_c4[i] + 1][a_row[i]] = v.y;
            As[a_c4[i] + 2][a_row[i]] = v.z;
            As[a_c4[i] + 3][a_row[i]] = v.w;
        }
#pragma unroll
        for (int i = 0; i < 2; i++) {
            int idx = tid + i * NTHREADS;
            int row = idx >> 5;
            int c4 = (idx & 31) * 4;
            float4 v = *(const float4*)(B + (size_t)(k0 + row) * HDIM + n0 + c4);
            *(float4*)&Bs[row][c4] = v;
        }
        __syncthreads();
#pragma unroll
        for (int k = 0; k < BK; k++) {
            float a[8], b[8];
#pragma unroll
            for (int i = 0; i < 8; i++) a[i] = As[k][ty * 8 + i];
#pragma unroll
            for (int j = 0; j < 8; j++) b[j] = Bs[k][tx * 8 + j];
#pragma unroll
            for (int i = 0; i < 8; i++)
#pragma unroll
                for (int j = 0; j < 8; j++) acc[i][j] += a[i] * b[j];
        }
        __syncthreads();
    }

#pragma unroll
    for (int i = 0; i < 8; i++) {
        int m = m0 + ty * 8 + i;
        if (m >= cnt) break;
        int t = g_tok_slot[base + m];
        float wt = g_wt_slot[base + m];
        float* orow = out + (size_t)t * HDIM + n0;
#pragma unroll
        for (int j = 0; j < 8; j++) {
            int n = tx * 8 + j;
            float v = wt * (acc[i][j] + b2[e * HDIM + n0 + n]);
            atomicAdd(&orow[n], v);
        }
    }
}

// ---------------- launch ----------------
extern "C" void kernel_launch(void* const* d_in, const int* in_sizes, int n_in,
                              void* d_out, int out_size) {
    const float* x   = (const float*)d_in[0];   // [4,2048,1024]
    const float* rw  = (const float*)d_in[1];   // [1024,8]
    const float* rb  = (const float*)d_in[2];   // [8]
    const float* w1  = (const float*)d_in[3];   // [8,1024,4096]
    const float* b1  = (const float*)d_in[4];   // [8,4096]
    const float* w2  = (const float*)d_in[5];   // [8,4096,1024]
    const float* b2  = (const float*)d_in[6];   // [8,1024]
    float* out = (float*)d_out;                 // [4,2048,1024]

    cudaMemsetAsync(out, 0, (size_t)out_size * sizeof(float));
    zero_counts_kernel<<<1, 32>>>();
    router_kernel<<<TOK / 8, dim3(32, 8)>>>(x, rw, rb);
    prefix_kernel<<<1, 32>>>();
    scatter_kernel<<<TOK / 256, 256>>>();

    dim3 g1(FDIM / BN, TOK / BM, NEXP);   // 32 x 64 x 8
    gemm1_kernel<<<g1, NTHREADS>>>(x, w1, b1);

    dim3 g2(HDIM / BN, TOK / BM, NEXP);   // 8 x 64 x 8
    gemm2_kernel<<<g2, NTHREADS>>>(w2, b2, out);
}

// round 3
// speedup vs baseline: 1.5010x; 1.5010x over previous
#include <cuda_runtime.h>
#include <cuda_bf16.h>
#include <math.h>
#include <stdint.h>

// ---------------- problem constants ----------------
#define TOK   8192
#define HDIM  1024
#define NEXP  8
#define FDIM  4096
#define NSLOT (TOK*2)

// ---------------- device scratch ----------------
__device__ int   g_count[NEXP];
__device__ int   g_cursor[NEXP];
__device__ int   g_offset[NEXP];
__device__ int   g_exp[TOK * 2];
__device__ float g_wt[TOK * 2];
__device__ int   g_tok_slot[NSLOT];
__device__ float g_wt_slot[NSLOT];

// bf16 split operands. A rows: [hi(K) | lo(K)], B rows (N-major): [hi(K) | lo(K)]
__device__ __nv_bfloat16 g_a1[(size_t)(NSLOT + 128) * (2 * HDIM)];
__device__ __nv_bfloat16 g_b1[(size_t)NEXP * FDIM * (2 * HDIM)];
__device__ __nv_bfloat16 g_a2[(size_t)(NSLOT + 128) * (2 * FDIM)];
__device__ __nv_bfloat16 g_b2[(size_t)NEXP * HDIM * (2 * FDIM)];

// ---------------- helpers ----------------
__device__ __forceinline__ uint32_t smem_u32(const void* p) {
    return (uint32_t)__cvta_generic_to_shared(p);
}

__device__ __forceinline__ void cp_async16(uint32_t dst, const void* src) {
    asm volatile("cp.async.cg.shared.global [%0], [%1], 16;" :: "r"(dst), "l"(src) : "memory");
}
__device__ __forceinline__ void cp_commit() {
    asm volatile("cp.async.commit_group;" ::: "memory");
}
template <int N>
__device__ __forceinline__ void cp_wait() {
    asm volatile("cp.async.wait_group %0;" :: "n"(N) : "memory");
}

__device__ __forceinline__ void ldsm_x4(uint32_t* r, uint32_t addr) {
    asm volatile("ldmatrix.sync.aligned.m8n8.x4.shared.b16 {%0,%1,%2,%3}, [%4];"
                 : "=r"(r[0]), "=r"(r[1]), "=r"(r[2]), "=r"(r[3]) : "r"(addr));
}

__device__ __forceinline__ void mma_bf16(float* c, const uint32_t* a, uint32_t b0, uint32_t b1) {
    asm volatile(
        "mma.sync.aligned.m16n8k16.row.col.f32.bf16.bf16.f32 "
        "{%0,%1,%2,%3}, {%4,%5,%6,%7}, {%8,%9}, {%0,%1,%2,%3};"
        : "+f"(c[0]), "+f"(c[1]), "+f"(c[2]), "+f"(c[3])
        : "r"(a[0]), "r"(a[1]), "r"(a[2]), "r"(a[3]), "r"(b0), "r"(b1));
}

__device__ __forceinline__ float gelu_exact(float v) {
    return 0.5f * v * (1.0f + erff(v * 0.70710678118654752f));
}

// ---------------- router / bookkeeping ----------------
__global__ void zero_counts_kernel() {
    int i = threadIdx.x;
    if (i < NEXP) g_count[i] = 0;
}

__global__ void router_kernel(const float* __restrict__ x,
                              const float* __restrict__ rw,
                              const float* __restrict__ rb) {
    int t = blockIdx.x * 8 + threadIdx.y;
    if (t >= TOK) return;
    int lane = threadIdx.x;
    float acc[8];
#pragma unroll
    for (int e = 0; e < 8; e++) acc[e] = 0.f;
    const float* xr = x + (size_t)t * HDIM;
    for (int h = lane; h < HDIM; h += 32) {
        float xv = xr[h];
        const float4 w0 = *(const float4*)(rw + h * 8);
        const float4 w1 = *(const float4*)(rw + h * 8 + 4);
        acc[0] += xv * w0.x; acc[1] += xv * w0.y;
        acc[2] += xv * w0.z; acc[3] += xv * w0.w;
        acc[4] += xv * w1.x; acc[5] += xv * w1.y;
        acc[6] += xv * w1.z; acc[7] += xv * w1.w;
    }
#pragma unroll
    for (int off = 16; off > 0; off >>= 1)
#pragma unroll
        for (int e = 0; e < 8; e++)
            acc[e] += __shfl_down_sync(0xffffffffu, acc[e], off);
    if (lane == 0) {
        float l[8];
#pragma unroll
        for (int e = 0; e < 8; e++) l[e] = acc[e] + rb[e];
        float mx = l[0];
#pragma unroll
        for (int e = 1; e < 8; e++) mx = fmaxf(mx, l[e]);
        float p[8];
#pragma unroll
        for (int e = 0; e < 8; e++) p[e] = __expf(l[e] - mx);
        int e1 = 0; float p1 = p[0];
#pragma unroll
        for (int e = 1; e < 8; e++) if (p[e] > p1) { p1 = p[e]; e1 = e; }
        int e2 = -1; float p2 = -1.f;
#pragma unroll
        for (int e = 0; e < 8; e++) if (e != e1 && p[e] > p2) { p2 = p[e]; e2 = e; }
        float inv = 1.f / (p1 + p2);
        g_exp[t * 2 + 0] = e1; g_wt[t * 2 + 0] = p1 * inv;
        g_exp[t * 2 + 1] = e2; g_wt[t * 2 + 1] = p2 * inv;
        atomicAdd(&g_count[e1], 1);
        atomicAdd(&g_count[e2], 1);
    }
}

__global__ void prefix_kernel() {
    if (threadIdx.x == 0) {
        int o = 0;
        for (int e = 0; e < NEXP; e++) { g_offset[e] = o; o += g_count[e]; g_cursor[e] = 0; }
    }
}

__global__ void scatter_kernel() {
    int t = blockIdx.x * blockDim.x + threadIdx.x;
    if (t >= TOK) return;
#pragma unroll
    for (int k = 0; k < 2; k++) {
        int e = g_exp[t * 2 + k];
        float w = g_wt[t * 2 + k];
        int pos = atomicAdd(&g_cursor[e], 1);
        int slot = g_offset[e] + pos;
        g_tok_slot[slot] = t;
        g_wt_slot[slot] = w;
    }
}

// ---------------- conversion kernels ----------------
__global__ void convx_kernel(const float* __restrict__ x) {
    int slot = blockIdx.x;
    int tid = threadIdx.x;
    int t = g_tok_slot[slot];
    const float4* xr = (const float4*)(x + (size_t)t * HDIM);
    __nv_bfloat162* hi = (__nv_bfloat162*)(g_a1 + (size_t)slot * 2048);
    __nv_bfloat162* lo = (__nv_bfloat162*)(g_a1 + (size_t)slot * 2048 + 1024);
    for (int i = tid; i < 256; i += 128) {
        float4 v = xr[i];
        __nv_bfloat16 h0 = __float2bfloat16(v.x), h1 = __float2bfloat16(v.y);
        __nv_bfloat16 h2 = __float2bfloat16(v.z), h3 = __float2bfloat16(v.w);
        __nv_bfloat162 hp0, hp1, lp0, lp1;
        hp0.x = h0; hp0.y = h1; hp1.x = h2; hp1.y = h3;
        lp0.x = __float2bfloat16(v.x - __bfloat162float(h0));
        lp0.y = __float2bfloat16(v.y - __bfloat162float(h1));
        lp1.x = __float2bfloat16(v.z - __bfloat162float(h2));
        lp1.y = __float2bfloat16(v.w - __bfloat162float(h3));
        hi[2 * i] = hp0; hi[2 * i + 1] = hp1;
        lo[2 * i] = lp0; lo[2 * i + 1] = lp1;
    }
}

// transpose + split: w [E][K][N] -> Bp [E][N][hi(K)|lo(K)]; which: 0->g_b1, 1->g_b2
__global__ void convw_kernel(const float* __restrict__ w, int which, int K, int N) {
    __shared__ float tile[32][33];
    __nv_bfloat16* Bp = which ? g_b2 : g_b1;
    int e = blockIdx.z;
    int n0 = blockIdx.x * 32, k0 = blockIdx.y * 32;
    const float* we = w + (size_t)e * K * N;
    __nv_bfloat16* Be = Bp + (size_t)e * N * 2 * K;
    int tx = threadIdx.x, ty = threadIdx.y;
#pragma unroll
    for (int r = 0; r < 32; r += 8)
        tile[ty + r][tx] = we[(size_t)(k0 + ty + r) * N + n0 + tx];
    __syncthreads();
#pragma unroll
    for (int r = 0; r < 32; r += 8) {
        float v = tile[tx][ty + r];
        int n = n0 + ty + r, k = k0 + tx;
        __nv_bfloat16 h = __float2bfloat16(v);
        Be[(size_t)n * 2 * K + k] = h;
        Be[(size_t)n * 2 * K + K + k] = __float2bfloat16(v - __bfloat162float(h));
    }
}

// ---------------- mma.sync GEMM ----------------
// CTA tile 128x128, BK=32 bf16. 8 warps: wm = wid&1 (64 M rows), wn = wid>>1 (32 N cols).
// Smem rows padded to 80 B (32 bf16 = 64 B data + 16 B pad): conflict-free ldmatrix.
#define ROWB 80
#define TILEB (128 * ROWB)           // 10240 B per operand tile

struct SmemT {
    __align__(128) char a[2][TILEB];
    __align__(128) char b[2][TILEB];
};

// one double-buffered K-chunk mainloop over 3 split terms
template <int KD>
__device__ __forceinline__ void mma_mainloop(
    const __nv_bfloat16* __restrict__ Aseg,   // 128 rows, stride 2*KD
    const __nv_bfloat16* __restrict__ Bseg,   // 128 rows, stride 2*KD
    SmemT* sm, float c[4][4][4], int tid, int lane, int wm, int wn)
{
    const int CPT = KD / 32;
    const int NCH = 3 * CPT;

    // cp.async source/dest mapping: 4 x 16B per thread per operand tile
    int r0 = tid >> 1;              // 0..127
    int j0 = (tid & 1) * 2;         // 0 or 2 (two consecutive 16B units)

    // ldmatrix lane addressing offsets (within a stage's operand tile)
    uint32_t a_off = (uint32_t)((wm * 64 + (lane & 15)) * ROWB + (lane >> 4) * 16);
    int bn = (lane & 7) + ((lane & 16) >> 1);
    uint32_t b_off = (uint32_t)((wn * 32 + bn) * ROWB + ((lane >> 3) & 1) * 16);

    uint32_t sa_u32[2] = { smem_u32(sm->a[0]), smem_u32(sm->a[1]) };
    uint32_t sb_u32[2] = { smem_u32(sm->b[0]), smem_u32(sm->b[1]) };

    auto issue_loads = [&](int c_idx, int s) {
        int t = c_idx / CPT;
        int kc = c_idx % CPT;
        int aoff = (t == 2 ? KD : 0) + kc * 32;
        int boff = (t == 1 ? KD : 0) + kc * 32;
        const __nv_bfloat16* arow = Aseg + (size_t)r0 * (2 * KD) + aoff + j0 * 8;
        const __nv_bfloat16* brow = Bseg + (size_t)r0 * (2 * KD) + boff + j0 * 8;
        uint32_t da = sa_u32[s] + r0 * ROWB + j0 * 16;
        uint32_t db = sb_u32[s] + r0 * ROWB + j0 * 16;
        cp_async16(da, arow);
        cp_async16(da + 16, arow + 8);
        cp_async16(db, brow);
        cp_async16(db + 16, brow + 8);
        cp_commit();
    };

    issue_loads(0, 0);

    for (int c_idx = 0; c_idx < NCH; c_idx++) {
        int s = c_idx & 1;
        if (c_idx + 1 < NCH) {
            issue_loads(c_idx + 1, s ^ 1);
            cp_wait<1>();
        } else {
            cp_wait<0>();
        }
        __syncthreads();

        uint32_t sa = sa_u32[s], sb = sb_u32[s];
#pragma unroll
        for (int ks = 0; ks < 2; ks++) {
            uint32_t a[4][4], b[2][4];
#pragma unroll
            for (int mt = 0; mt < 4; mt++)
                ldsm_x4(a[mt], sa + a_off + mt * (16 * ROWB) + ks * 32);
#pragma unroll
            for (int nt = 0; nt < 2; nt++)
                ldsm_x4(b[nt], sb + b_off + nt * (16 * ROWB) + ks * 32);
#pragma unroll
            for (int mt = 0; mt < 4; mt++) {
#pragma unroll
                for (int j = 0; j < 4; j++)
                    mma_bf16(c[mt][j], a[mt], b[j >> 1][(j & 1) * 2], b[j >> 1][(j & 1) * 2 + 1]);
            }
        }
        __syncthreads();
    }
}

__global__ void __launch_bounds__(256, 1)
gemm1_mma(const float* __restrict__ b1) {
    const int e = blockIdx.z;
    const int cnt = g_count[e];
    const int m0 = blockIdx.y * 128;
    if (m0 >= cnt) return;
    const int n0 = blockIdx.x * 128;
    const int base = g_offset[e];

    __shared__ SmemT sm;
    int tid = threadIdx.x, lane = tid & 31, wid = tid >> 5;
    int wm = wid & 1, wn = wid >> 1;

    const __nv_bfloat16* Aseg = g_a1 + (size_t)(base + m0) * (2 * HDIM);
    const __nv_bfloat16* Bseg = g_b1 + ((size_t)e * FDIM + n0) * (2 * HDIM);

    float c[4][4][4];
#pragma unroll
    for (int i = 0; i < 4; i++)
#pragma unroll
        for (int j = 0; j < 4; j++)
#pragma unroll
            for (int k = 0; k < 4; k++) c[i][j][k] = 0.f;

    mma_mainloop<HDIM>(Aseg, Bseg, &sm, c, tid, lane, wm, wn);

    // epilogue: gelu(acc + b1) -> split -> g_a2 rows [hi|lo]
    int n_base = n0 + wn * 32 + (lane & 3) * 2;
    int m_base = m0 + wm * 64 + (lane >> 2);
#pragma unroll
    for (int mt = 0; mt < 4; mt++) {
#pragma unroll
        for (int half = 0; half < 2; half++) {
            int m = m_base + mt * 16 + half * 8;
            if (m >= cnt) continue;
            __nv_bfloat16* rowp = g_a2 + (size_t)(base + m) * (2 * FDIM);
#pragma unroll
            for (int j = 0; j < 4; j++) {
                int n = n_base + j * 8;
                float2 bv = *(const float2*)(b1 + e * FDIM + n);
                float g0 = gelu_exact(c[mt][j][half * 2 + 0] + bv.x);
                float g1 = gelu_exact(c[mt][j][half * 2 + 1] + bv.y);
                __nv_bfloat16 h0 = __float2bfloat16(g0);
                __nv_bfloat16 h1 = __float2bfloat16(g1);
                __nv_bfloat162 hp, lp;
                hp.x = h0; hp.y = h1;
                lp.x = __float2bfloat16(g0 - __bfloat162float(h0));
                lp.y = __float2bfloat16(g1 - __bfloat162float(h1));
                *(__nv_bfloat162*)(rowp + n) = hp;
                *(__nv_bfloat162*)(rowp + FDIM + n) = lp;
            }
        }
    }
}

__global__ void __launch_bounds__(256, 1)
gemm2_mma(const float* __restrict__ b2, float* __restrict__ out) {
    const int e = blockIdx.z;
    const int cnt = g_count[e];
    const int m0 = blockIdx.y * 128;
    if (m0 >= cnt) return;
    const int n0 = blockIdx.x * 128;
    const int base = g_offset[e];

    __shared__ SmemT sm;
    int tid = threadIdx.x, lane = tid & 31, wid = tid >> 5;
    int wm = wid & 1, wn = wid >> 1;

    const __nv_bfloat16* Aseg = g_a2 + (size_t)(base + m0) * (2 * FDIM);
    const __nv_bfloat16* Bseg = g_b2 + ((size_t)e * HDIM + n0) * (2 * FDIM);

    float c[4][4][4];
#pragma unroll
    for (int i = 0; i < 4; i++)
#pragma unroll
        for (int j = 0; j < 4; j++)
#pragma unroll
            for (int k = 0; k < 4; k++) c[i][j][k] = 0.f;

    mma_mainloop<FDIM>(Aseg, Bseg, &sm, c, tid, lane, wm, wn);

    // epilogue: out[tok] += wt * (acc + b2)
    int n_base = n0 + wn * 32 + (lane & 3) * 2;
    int m_base = m0 + wm * 64 + (lane >> 2);
#pragma unroll
    for (int mt = 0; mt < 4; mt++) {
#pragma unroll
        for (int half = 0; half < 2; half++) {
            int m = m_base + mt * 16 + half * 8;
            if (m >= cnt) continue;
            int t = g_tok_slot[base + m];
            float wt = g_wt_slot[base + m];
            float* orow = out + (size_t)t * HDIM;
#pragma unroll
            for (int j = 0; j < 4; j++) {
                int n = n_base + j * 8;
                float2 bv = *(const float2*)(b2 + e * HDIM + n);
                atomicAdd(&orow[n],     wt * (c[mt][j][half * 2 + 0] + bv.x));
                atomicAdd(&orow[n + 1], wt * (c[mt][j][half * 2 + 1] + bv.y));
            }
        }
    }
}

// ---------------- launch ----------------
extern "C" void kernel_launch(void* const* d_in, const int* in_sizes, int n_in,
                              void* d_out, int out_size) {
    const float* x  = (const float*)d_in[0];
    const float* rw = (const float*)d_in[1];
    const float* rb = (const float*)d_in[2];
    const float* w1 = (const float*)d_in[3];
    const float* b1 = (const float*)d_in[4];
    const float* w2 = (const float*)d_in[5];
    const float* b2 = (const float*)d_in[6];
    float* out = (float*)d_out;

    cudaMemsetAsync(out, 0, (size_t)out_size * sizeof(float));
    zero_counts_kernel<<<1, 32>>>();
    router_kernel<<<TOK / 8, dim3(32, 8)>>>(x, rw, rb);
    prefix_kernel<<<1, 32>>>();
    scatter_kernel<<<TOK / 256, 256>>>();
    convx_kernel<<<NSLOT, 128>>>(x);
    convw_kernel<<<dim3(FDIM / 32, HDIM / 32, NEXP), dim3(32, 8)>>>(w1, 0, HDIM, FDIM);
    convw_kernel<<<dim3(HDIM / 32, FDIM / 32, NEXP), dim3(32, 8)>>>(w2, 1, FDIM, HDIM);

    gemm1_mma<<<dim3(FDIM / 128, TOK / 128, NEXP), 256>>>(b1);
    gemm2_mma<<<dim3(HDIM / 128, TOK / 128, NEXP), 256>>>(b2, out);
}

// round 4
// speedup vs baseline: 4.8939x; 3.2605x over previous
#include <cuda_runtime.h>
#include <cuda_fp16.h>
#include <math.h>
#include <stdint.h>

// ---------------- problem constants ----------------
#define TOK   8192
#define HDIM  1024
#define NEXP  8
#define FDIM  4096
#define NSLOT (TOK*2)

// ---------------- device scratch ----------------
__device__ int   g_count[NEXP];
__device__ int   g_cursor[NEXP];
__device__ int   g_offset[NEXP];
__device__ int   g_exp[TOK * 2];
__device__ float g_wt[TOK * 2];
__device__ int   g_tok_slot[NSLOT];
__device__ float g_wt_slot[NSLOT];

// fp16 operands (K-major rows). +128 row pad so OOB tile reads stay in-bounds.
__device__ __half g_a1[(size_t)(NSLOT + 128) * HDIM];            // 33.8 MB
__device__ __half g_b1[(size_t)NEXP * FDIM * HDIM];              // 67 MB  [E][N][K]
__device__ __half g_a2[(size_t)(NSLOT + 128) * FDIM];            // 135 MB
__device__ __half g_b2[(size_t)NEXP * HDIM * FDIM];              // 67 MB  [E][N][K]

// ---------------- helpers ----------------
__device__ __forceinline__ uint32_t smem_u32(const void* p) {
    return (uint32_t)__cvta_generic_to_shared(p);
}
__device__ __forceinline__ void cp_async16(uint32_t dst, const void* src) {
    asm volatile("cp.async.cg.shared.global [%0], [%1], 16;" :: "r"(dst), "l"(src) : "memory");
}
__device__ __forceinline__ void cp_commit() {
    asm volatile("cp.async.commit_group;" ::: "memory");
}
template <int N>
__device__ __forceinline__ void cp_wait() {
    asm volatile("cp.async.wait_group %0;" :: "n"(N) : "memory");
}
__device__ __forceinline__ void ldsm_x4(uint32_t* r, uint32_t addr) {
    asm volatile("ldmatrix.sync.aligned.m8n8.x4.shared.b16 {%0,%1,%2,%3}, [%4];"
                 : "=r"(r[0]), "=r"(r[1]), "=r"(r[2]), "=r"(r[3]) : "r"(addr));
}
__device__ __forceinline__ void mma_fp16(float* c, const uint32_t* a, uint32_t b0, uint32_t b1) {
    asm volatile(
        "mma.sync.aligned.m16n8k16.row.col.f32.f16.f16.f32 "
        "{%0,%1,%2,%3}, {%4,%5,%6,%7}, {%8,%9}, {%0,%1,%2,%3};"
        : "+f"(c[0]), "+f"(c[1]), "+f"(c[2]), "+f"(c[3])
        : "r"(a[0]), "r"(a[1]), "r"(a[2]), "r"(a[3]), "r"(b0), "r"(b1));
}
__device__ __forceinline__ float gelu_exact(float v) {
    return 0.5f * v * (1.0f + erff(v * 0.70710678118654752f));
}

// ---------------- router / bookkeeping ----------------
__global__ void zero_counts_kernel() {
    int i = threadIdx.x;
    if (i < NEXP) g_count[i] = 0;
}

__global__ void router_kernel(const float* __restrict__ x,
                              const float* __restrict__ rw,
                              const float* __restrict__ rb) {
    int t = blockIdx.x * 8 + threadIdx.y;
    if (t >= TOK) return;
    int lane = threadIdx.x;
    float acc[8];
#pragma unroll
    for (int e = 0; e < 8; e++) acc[e] = 0.f;
    const float* xr = x + (size_t)t * HDIM;
    for (int h = lane; h < HDIM; h += 32) {
        float xv = xr[h];
        const float4 w0 = *(const float4*)(rw + h * 8);
        const float4 w1 = *(const float4*)(rw + h * 8 + 4);
        acc[0] += xv * w0.x; acc[1] += xv * w0.y;
        acc[2] += xv * w0.z; acc[3] += xv * w0.w;
        acc[4] += xv * w1.x; acc[5] += xv * w1.y;
        acc[6] += xv * w1.z; acc[7] += xv * w1.w;
    }
#pragma unroll
    for (int off = 16; off > 0; off >>= 1)
#pragma unroll
        for (int e = 0; e < 8; e++)
            acc[e] += __shfl_down_sync(0xffffffffu, acc[e], off);
    if (lane == 0) {
        float l[8];
#pragma unroll
        for (int e = 0; e < 8; e++) l[e] = acc[e] + rb[e];
        float mx = l[0];
#pragma unroll
        for (int e = 1; e < 8; e++) mx = fmaxf(mx, l[e]);
        float p[8];
#pragma unroll
        for (int e = 0; e < 8; e++) p[e] = __expf(l[e] - mx);
        int e1 = 0; float p1 = p[0];
#pragma unroll
        for (int e = 1; e < 8; e++) if (p[e] > p1) { p1 = p[e]; e1 = e; }
        int e2 = -1; float p2 = -1.f;
#pragma unroll
        for (int e = 0; e < 8; e++) if (e != e1 && p[e] > p2) { p2 = p[e]; e2 = e; }
        float inv = 1.f / (p1 + p2);
        g_exp[t * 2 + 0] = e1; g_wt[t * 2 + 0] = p1 * inv;
        g_exp[t * 2 + 1] = e2; g_wt[t * 2 + 1] = p2 * inv;
        atomicAdd(&g_count[e1], 1);
        atomicAdd(&g_count[e2], 1);
    }
}

__global__ void prefix_kernel() {
    if (threadIdx.x == 0) {
        int o = 0;
        for (int e = 0; e < NEXP; e++) { g_offset[e] = o; o += g_count[e]; g_cursor[e] = 0; }
    }
}

__global__ void scatter_kernel() {
    int t = blockIdx.x * blockDim.x + threadIdx.x;
    if (t >= TOK) return;
#pragma unroll
    for (int k = 0; k < 2; k++) {
        int e = g_exp[t * 2 + k];
        float w = g_wt[t * 2 + k];
        int pos = atomicAdd(&g_cursor[e], 1);
        int slot = g_offset[e] + pos;
        g_tok_slot[slot] = t;
        g_wt_slot[slot] = w;
    }
}

// ---------------- conversion kernels ----------------
// gather x rows -> g_a1 [slot][1024] fp16
__global__ void convx_kernel(const float* __restrict__ x) {
    int slot = blockIdx.x;
    int tid = threadIdx.x;   // 128
    int t = g_tok_slot[slot];
    const float4* xr = (const float4*)(x + (size_t)t * HDIM);
    __half2* dst = (__half2*)(g_a1 + (size_t)slot * HDIM);
    for (int i = tid; i < 256; i += 128) {
        float4 v = xr[i];
        dst[2 * i]     = __floats2half2_rn(v.x, v.y);
        dst[2 * i + 1] = __floats2half2_rn(v.z, v.w);
    }
}

// transpose: w [E][K][N] -> Bp [E][N][K] fp16; which: 0->g_b1, 1->g_b2
__global__ void convw_kernel(const float* __restrict__ w, int which, int K, int N) {
    __shared__ float tile[32][33];
    __half* Bp = which ? g_b2 : g_b1;
    int e = blockIdx.z;
    int n0 = blockIdx.x * 32, k0 = blockIdx.y * 32;
    const float* we = w + (size_t)e * K * N;
    __half* Be = Bp + (size_t)e * N * K;
    int tx = threadIdx.x, ty = threadIdx.y;  // 32 x 8
#pragma unroll
    for (int r = 0; r < 32; r += 8)
        tile[ty + r][tx] = we[(size_t)(k0 + ty + r) * N + n0 + tx];
    __syncthreads();
#pragma unroll
    for (int r = 0; r < 32; r += 8) {
        int n = n0 + ty + r, k = k0 + tx;
        Be[(size_t)n * K + k] = __float2half_rn(tile[tx][ty + r]);
    }
}

// ---------------- mma.sync GEMM ----------------
// CTA tile 128x128, BK=32 fp16, 3-stage cp.async pipeline, 2 CTAs/SM.
// 8 warps: wm = wid&1 (64 M rows), wn = wid>>1 (32 N cols).
#define ROWB 80                       // 64 B data + 16 B pad per 32-elem row
#define TILEB (128 * ROWB)            // 10240 B per operand per stage
#define STAGES 3
#define SMEM_DYN (STAGES * 2 * TILEB) // 61440 B

template <int KD>
__device__ __forceinline__ void mma_mainloop(
    const __half* __restrict__ Aseg,   // 128 rows, stride KD
    const __half* __restrict__ Bseg,   // 128 rows, stride KD
    char* smb, float c[4][4][4], int tid, int lane, int wm, int wn)
{
    const int NCH = KD / 32;

    int r0 = tid >> 1;                  // 0..127
    int j0 = (tid & 1) * 2;             // 16B-unit index: 0 or 2

    uint32_t sa[STAGES], sb[STAGES];
#pragma unroll
    for (int s = 0; s < STAGES; s++) {
        sa[s] = smem_u32(smb + s * TILEB);
        sb[s] = smem_u32(smb + (STAGES + s) * TILEB);
    }

    uint32_t a_off = (uint32_t)((wm * 64 + (lane & 15)) * ROWB + (lane >> 4) * 16);
    int bn = (lane & 7) + ((lane & 16) >> 1);
    uint32_t b_off = (uint32_t)((wn * 32 + bn) * ROWB + ((lane >> 3) & 1) * 16);

    auto issue = [&](int ci, int s) {
        const __half* ar = Aseg + (size_t)r0 * KD + ci * 32 + j0 * 8;
        const __half* br = Bseg + (size_t)r0 * KD + ci * 32 + j0 * 8;
        uint32_t da = sa[s] + r0 * ROWB + j0 * 16;
        uint32_t db = sb[s] + r0 * ROWB + j0 * 16;
        cp_async16(da, ar);
        cp_async16(da + 16, ar + 8);
        cp_async16(db, br);
        cp_async16(db + 16, br + 8);
    };

    issue(0, 0); cp_commit();
    if (NCH > 1) issue(1, 1);
    cp_commit();

    for (int ci = 0; ci < NCH; ci++) {
        if (ci + 2 < NCH) issue(ci + 2, (ci + 2) % STAGES);
        cp_commit();
        cp_wait<2>();
        __syncthreads();

        int s = ci % STAGES;
        uint32_t sav = sa[s], sbv = sb[s];
#pragma unroll
        for (int ks = 0; ks < 2; ks++) {
            uint32_t a[4][4], b[2][4];
#pragma unroll
            for (int mt = 0; mt < 4; mt++)
                ldsm_x4(a[mt], sav + a_off + mt * (16 * ROWB) + ks * 32);
#pragma unroll
            for (int nt = 0; nt < 2; nt++)
                ldsm_x4(b[nt], sbv + b_off + nt * (16 * ROWB) + ks * 32);
#pragma unroll
            for (int mt = 0; mt < 4; mt++) {
#pragma unroll
                for (int j = 0; j < 4; j++)
                    mma_fp16(c[mt][j], a[mt], b[j >> 1][(j & 1) * 2], b[j >> 1][(j & 1) * 2 + 1]);
            }
        }
        __syncthreads();
    }
}

__global__ void __launch_bounds__(256, 2)
gemm1_mma(const float* __restrict__ b1) {
    const int e = blockIdx.z;
    const int cnt = g_count[e];
    const int m0 = blockIdx.y * 128;
    if (m0 >= cnt) return;
    const int n0 = blockIdx.x * 128;
    const int base = g_offset[e];

    extern __shared__ char smb[];
    int tid = threadIdx.x, lane = tid & 31, wid = tid >> 5;
    int wm = wid & 1, wn = wid >> 1;

    const __half* Aseg = g_a1 + (size_t)(base + m0) * HDIM;
    const __half* Bseg = g_b1 + ((size_t)e * FDIM + n0) * HDIM;

    float c[4][4][4];
#pragma unroll
    for (int i = 0; i < 4; i++)
#pragma unroll
        for (int j = 0; j < 4; j++)
#pragma unroll
            for (int k = 0; k < 4; k++) c[i][j][k] = 0.f;

    mma_mainloop<HDIM>(Aseg, Bseg, smb, c, tid, lane, wm, wn);

    // epilogue: gelu(acc + b1) -> fp16 -> g_a2
    int n_base = n0 + wn * 32 + (lane & 3) * 2;
    int m_base = m0 + wm * 64 + (lane >> 2);
#pragma unroll
    for (int mt = 0; mt < 4; mt++) {
#pragma unroll
        for (int half = 0; half < 2; half++) {
            int m = m_base + mt * 16 + half * 8;
            if (m >= cnt) continue;
            __half* rowp = g_a2 + (size_t)(base + m) * FDIM;
#pragma unroll
            for (int j = 0; j < 4; j++) {
                int n = n_base + j * 8;
                float2 bv = *(const float2*)(b1 + e * FDIM + n);
                float g0 = gelu_exact(c[mt][j][half * 2 + 0] + bv.x);
                float g1 = gelu_exact(c[mt][j][half * 2 + 1] + bv.y);
                *(__half2*)(rowp + n) = __floats2half2_rn(g0, g1);
            }
        }
    }
}

__global__ void __launch_bounds__(256, 2)
gemm2_mma(const float* __restrict__ b2, float* __restrict__ out) {
    const int e = blockIdx.z;
    const int cnt = g_count[e];
    const int m0 = blockIdx.y * 128;
    if (m0 >= cnt) return;
    const int n0 = blockIdx.x * 128;
    const int base = g_offset[e];

    extern __shared__ char smb[];
    int tid = threadIdx.x, lane = tid & 31, wid = tid >> 5;
    int wm = wid & 1, wn = wid >> 1;

    const __half* Aseg = g_a2 + (size_t)(base + m0) * FDIM;
    const __half* Bseg = g_b2 + ((size_t)e * HDIM + n0) * FDIM;

    float c[4][4][4];
#pragma unroll
    for (int i = 0; i < 4; i++)
#pragma unroll
        for (int j = 0; j < 4; j++)
#pragma unroll
            for (int k = 0; k < 4; k++) c[i][j][k] = 0.f;

    mma_mainloop<FDIM>(Aseg, Bseg, smb, c, tid, lane, wm, wn);

    // epilogue: out[tok] += wt * (acc + b2)
    int n_base = n0 + wn * 32 + (lane & 3) * 2;
    int m_base = m0 + wm * 64 + (lane >> 2);
#pragma unroll
    for (int mt = 0; mt < 4; mt++) {
#pragma unroll
        for (int half = 0; half < 2; half++) {
            int m = m_base + mt * 16 + half * 8;
            if (m >= cnt) continue;
            int t = g_tok_slot[base + m];
            float wt = g_wt_slot[base + m];
            float* orow = out + (size_t)t * HDIM;
#pragma unroll
            for (int j = 0; j < 4; j++) {
                int n = n_base + j * 8;
                float2 bv = *(const float2*)(b2 + e * HDIM + n);
                atomicAdd(&orow[n],     wt * (c[mt][j][half * 2 + 0] + bv.x));
                atomicAdd(&orow[n + 1], wt * (c[mt][j][half * 2 + 1] + bv.y));
            }
        }
    }
}

// ---------------- launch ----------------
extern "C" void kernel_launch(void* const* d_in, const int* in_sizes, int n_in,
                              void* d_out, int out_size) {
    const float* x  = (const float*)d_in[0];
    const float* rw = (const float*)d_in[1];
    const float* rb = (const float*)d_in[2];
    const float* w1 = (const float*)d_in[3];
    const float* b1 = (const float*)d_in[4];
    const float* w2 = (const float*)d_in[5];
    const float* b2 = (const float*)d_in[6];
    float* out = (float*)d_out;

    static int configured = 0;
    if (!configured) {
        cudaFuncSetAttribute(gemm1_mma, cudaFuncAttributeMaxDynamicSharedMemorySize, SMEM_DYN);
        cudaFuncSetAttribute(gemm2_mma, cudaFuncAttributeMaxDynamicSharedMemorySize, SMEM_DYN);
        configured = 1;
    }

    cudaMemsetAsync(out, 0, (size_t)out_size * sizeof(float));
    zero_counts_kernel<<<1, 32>>>();
    router_kernel<<<TOK / 8, dim3(32, 8)>>>(x, rw, rb);
    prefix_kernel<<<1, 32>>>();
    scatter_kernel<<<TOK / 256, 256>>>();
    convx_kernel<<<NSLOT, 128>>>(x);
    convw_kernel<<<dim3(FDIM / 32, HDIM / 32, NEXP), dim3(32, 8)>>>(w1, 0, HDIM, FDIM);
    convw_kernel<<<dim3(HDIM / 32, FDIM / 32, NEXP), dim3(32, 8)>>>(w2, 1, FDIM, HDIM);

    gemm1_mma<<<dim3(FDIM / 128, TOK / 128, NEXP), 256, SMEM_DYN>>>(b1);
    gemm2_mma<<<dim3(HDIM / 128, TOK / 128, NEXP), 256, SMEM_DYN>>>(b2, out);
}

// round 5
// speedup vs baseline: 5.0931x; 1.0407x over previous
#include <cuda_runtime.h>
#include <cuda_fp16.h>
#include <math.h>
#include <stdint.h>

// ---------------- problem constants ----------------
#define TOK   8192
#define HDIM  1024
#define NEXP  8
#define FDIM  4096
#define NSLOT (TOK*2)

// ---------------- device scratch ----------------
__device__ int   g_count[NEXP];
__device__ int   g_cursor[NEXP];
__device__ int   g_offset[NEXP];
__device__ int   g_exp[TOK * 2];
__device__ float g_wt[TOK * 2];
__device__ int   g_tok_slot[NSLOT];
__device__ float g_wt_slot[NSLOT];

// fp16 operands (K-major rows). +128 row pad so OOB tile reads stay in-bounds.
__device__ __half g_a1[(size_t)(NSLOT + 128) * HDIM];
__device__ __half g_b1[(size_t)NEXP * FDIM * HDIM];              // [E][N][K]
__device__ __half g_a2[(size_t)(NSLOT + 128) * FDIM];
__device__ __half g_b2[(size_t)NEXP * HDIM * FDIM];              // [E][N][K]

// ---------------- helpers ----------------
__device__ __forceinline__ uint32_t smem_u32(const void* p) {
    return (uint32_t)__cvta_generic_to_shared(p);
}
__device__ __forceinline__ void cp_async16(uint32_t dst, const void* src) {
    asm volatile("cp.async.cg.shared.global [%0], [%1], 16;" :: "r"(dst), "l"(src) : "memory");
}
__device__ __forceinline__ void cp_commit() {
    asm volatile("cp.async.commit_group;" ::: "memory");
}
template <int N>
__device__ __forceinline__ void cp_wait() {
    asm volatile("cp.async.wait_group %0;" :: "n"(N) : "memory");
}
__device__ __forceinline__ void ldsm_x4(uint32_t* r, uint32_t addr) {
    asm volatile("ldmatrix.sync.aligned.m8n8.x4.shared.b16 {%0,%1,%2,%3}, [%4];"
                 : "=r"(r[0]), "=r"(r[1]), "=r"(r[2]), "=r"(r[3]) : "r"(addr));
}
__device__ __forceinline__ void mma_fp16(float* c, const uint32_t* a, uint32_t b0, uint32_t b1) {
    asm volatile(
        "mma.sync.aligned.m16n8k16.row.col.f32.f16.f16.f32 "
        "{%0,%1,%2,%3}, {%4,%5,%6,%7}, {%8,%9}, {%0,%1,%2,%3};"
        : "+f"(c[0]), "+f"(c[1]), "+f"(c[2]), "+f"(c[3])
        : "r"(a[0]), "r"(a[1]), "r"(a[2]), "r"(a[3]), "r"(b0), "r"(b1));
}
__device__ __forceinline__ float gelu_exact(float v) {
    return 0.5f * v * (1.0f + erff(v * 0.70710678118654752f));
}

// ---------------- router / bookkeeping ----------------
__global__ void zero_counts_kernel() {
    int i = threadIdx.x;
    if (i < NEXP) g_count[i] = 0;
}

__global__ void router_kernel(const float* __restrict__ x,
                              const float* __restrict__ rw,
                              const float* __restrict__ rb) {
    int t = blockIdx.x * 8 + threadIdx.y;
    if (t >= TOK) return;
    int lane = threadIdx.x;
    float acc[8];
#pragma unroll
    for (int e = 0; e < 8; e++) acc[e] = 0.f;
    const float* xr = x + (size_t)t * HDIM;
    for (int h = lane; h < HDIM; h += 32) {
        float xv = xr[h];
        const float4 w0 = *(const float4*)(rw + h * 8);
        const float4 w1 = *(const float4*)(rw + h * 8 + 4);
        acc[0] += xv * w0.x; acc[1] += xv * w0.y;
        acc[2] += xv * w0.z; acc[3] += xv * w0.w;
        acc[4] += xv * w1.x; acc[5] += xv * w1.y;
        acc[6] += xv * w1.z; acc[7] += xv * w1.w;
    }
#pragma unroll
    for (int off = 16; off > 0; off >>= 1)
#pragma unroll
        for (int e = 0; e < 8; e++)
            acc[e] += __shfl_down_sync(0xffffffffu, acc[e], off);
    if (lane == 0) {
        float l[8];
#pragma unroll
        for (int e = 0; e < 8; e++) l[e] = acc[e] + rb[e];
        float mx = l[0];
#pragma unroll
        for (int e = 1; e < 8; e++) mx = fmaxf(mx, l[e]);
        float p[8];
#pragma unroll
        for (int e = 0; e < 8; e++) p[e] = __expf(l[e] - mx);
        int e1 = 0; float p1 = p[0];
#pragma unroll
        for (int e = 1; e < 8; e++) if (p[e] > p1) { p1 = p[e]; e1 = e; }
        int e2 = -1; float p2 = -1.f;
#pragma unroll
        for (int e = 0; e < 8; e++) if (e != e1 && p[e] > p2) { p2 = p[e]; e2 = e; }
        float inv = 1.f / (p1 + p2);
        g_exp[t * 2 + 0] = e1; g_wt[t * 2 + 0] = p1 * inv;
        g_exp[t * 2 + 1] = e2; g_wt[t * 2 + 1] = p2 * inv;
        atomicAdd(&g_count[e1], 1);
        atomicAdd(&g_count[e2], 1);
    }
}

__global__ void prefix_kernel() {
    if (threadIdx.x == 0) {
        int o = 0;
        for (int e = 0; e < NEXP; e++) { g_offset[e] = o; o += g_count[e]; g_cursor[e] = 0; }
    }
}

__global__ void scatter_kernel() {
    int t = blockIdx.x * blockDim.x + threadIdx.x;
    if (t >= TOK) return;
#pragma unroll
    for (int k = 0; k < 2; k++) {
        int e = g_exp[t * 2 + k];
        float w = g_wt[t * 2 + k];
        int pos = atomicAdd(&g_cursor[e], 1);
        int slot = g_offset[e] + pos;
        g_tok_slot[slot] = t;
        g_wt_slot[slot] = w;
    }
}

// ---------------- conversion kernels ----------------
__global__ void convx_kernel(const float* __restrict__ x) {
    int slot = blockIdx.x;
    int tid = threadIdx.x;   // 128
    int t = g_tok_slot[slot];
    const float4* xr = (const float4*)(x + (size_t)t * HDIM);
    __half2* dst = (__half2*)(g_a1 + (size_t)slot * HDIM);
    for (int i = tid; i < 256; i += 128) {
        float4 v = xr[i];
        dst[2 * i]     = __floats2half2_rn(v.x, v.y);
        dst[2 * i + 1] = __floats2half2_rn(v.z, v.w);
    }
}

// transpose: w [E][K][N] -> Bp [E][N][K] fp16; which: 0->g_b1, 1->g_b2
__global__ void convw_kernel(const float* __restrict__ w, int which, int K, int N) {
    __shared__ float tile[32][33];
    __half* Bp = which ? g_b2 : g_b1;
    int e = blockIdx.z;
    int n0 = blockIdx.x * 32, k0 = blockIdx.y * 32;
    const float* we = w + (size_t)e * K * N;
    __half* Be = Bp + (size_t)e * N * K;
    int tx = threadIdx.x, ty = threadIdx.y;  // 32 x 8
#pragma unroll
    for (int r = 0; r < 32; r += 8)
        tile[ty + r][tx] = we[(size_t)(k0 + ty + r) * N + n0 + tx];
    __syncthreads();
#pragma unroll
    for (int r = 0; r < 32; r += 8) {
        int n = n0 + ty + r, k = k0 + tx;
        Be[(size_t)n * K + k] = __float2half_rn(tile[tx][ty + r]);
    }
}

// ---------------- mma.sync GEMM ----------------
// CTA tile 128x256, warp tile 64x64 (8 warps 2x4), BK=32 fp16.
// 4-stage cp.async pipeline, single __syncthreads per chunk, 1 CTA/SM.
#define ROWB 80                           // 64 B data + 16 B pad per 32-col row
#define A_TILEB (128 * ROWB)              // 10240
#define B_TILEB (256 * ROWB)              // 20480
#define STAGES 4
#define SMEM_DYN (STAGES * (A_TILEB + B_TILEB))   // 122880 B

template <int KD>
__device__ __forceinline__ void mma_mainloop(
    const __half* __restrict__ Aseg,   // 128 rows, stride KD
    const __half* __restrict__ Bseg,   // 256 rows, stride KD
    char* smb, float c[4][8][4], int tid, int lane, int wm, int wn)
{
    const int NCH = KD / 32;

    uint32_t sa[STAGES], sb[STAGES];
#pragma unroll
    for (int s = 0; s < STAGES; s++) {
        sa[s] = smem_u32(smb + s * (A_TILEB + B_TILEB));
        sb[s] = sa[s] + A_TILEB;
    }

    // A: 512 16B units (2/thread, stride 256); B: 1024 units (row per thread)
    int a_r0 = tid >> 2, a_c0 = tid & 3;       // unit tid: row tid>>2, col unit tid&3
    // ldmatrix offsets
    uint32_t a_off = (uint32_t)((wm * 64 + (lane & 15)) * ROWB + (lane >> 4) * 16);
    int bn = (lane & 7) + ((lane & 16) >> 1);
    uint32_t b_off = (uint32_t)((wn * 64 + bn) * ROWB + ((lane >> 3) & 1) * 16);

    auto issue = [&](int ci, int s) {
        int koff = ci * 32;
        // A tile: 128 x 32 fp16
        {
            const __half* ar = Aseg + (size_t)a_r0 * KD + koff + a_c0 * 8;
            uint32_t da = sa[s] + a_r0 * ROWB + a_c0 * 16;
            cp_async16(da, ar);
            cp_async16(da + 64 * ROWB, ar + (size_t)64 * KD);
        }
        // B tile: 256 x 32 fp16, one row per thread
        {
            const __half* br = Bseg + (size_t)tid * KD + koff;
            uint32_t db = sb[s] + tid * ROWB;
            cp_async16(db, br);
            cp_async16(db + 16, br + 8);
            cp_async16(db + 32, br + 16);
            cp_async16(db + 48, br + 24);
        }
    };

    issue(0, 0); cp_commit();
    issue(1, 1); cp_commit();
    issue(2, 2); cp_commit();

    for (int ci = 0; ci < NCH; ci++) {
        cp_wait<2>();
        __syncthreads();
        if (ci + 3 < NCH) issue(ci + 3, (ci + 3) % STAGES);
        cp_commit();

        int s = ci % STAGES;
        uint32_t sav = sa[s], sbv = sb[s];
#pragma unroll
        for (int ks = 0; ks < 2; ks++) {
            uint32_t a[4][4], b[4][4];
#pragma unroll
            for (int mt = 0; mt < 4; mt++)
                ldsm_x4(a[mt], sav + a_off + mt * (16 * ROWB) + ks * 32);
#pragma unroll
            for (int nt = 0; nt < 4; nt++)
                ldsm_x4(b[nt], sbv + b_off + nt * (16 * ROWB) + ks * 32);
#pragma unroll
            for (int mt = 0; mt < 4; mt++) {
#pragma unroll
                for (int j = 0; j < 8; j++)
                    mma_fp16(c[mt][j], a[mt], b[j >> 1][(j & 1) * 2], b[j >> 1][(j & 1) * 2 + 1]);
            }
        }
    }
}

__global__ void __launch_bounds__(256, 1)
gemm1_mma(const float* __restrict__ b1) {
    const int e = blockIdx.z;
    const int cnt = g_count[e];
    const int m0 = blockIdx.y * 128;
    if (m0 >= cnt) return;
    const int n0 = blockIdx.x * 256;
    const int base = g_offset[e];

    extern __shared__ char smb[];
    int tid = threadIdx.x, lane = tid & 31, wid = tid >> 5;
    int wm = wid & 1, wn = wid >> 1;

    const __half* Aseg = g_a1 + (size_t)(base + m0) * HDIM;
    const __half* Bseg = g_b1 + ((size_t)e * FDIM + n0) * HDIM;

    float c[4][8][4];
#pragma unroll
    for (int i = 0; i < 4; i++)
#pragma unroll
        for (int j = 0; j < 8; j++)
#pragma unroll
            for (int k = 0; k < 4; k++) c[i][j][k] = 0.f;

    mma_mainloop<HDIM>(Aseg, Bseg, smb, c, tid, lane, wm, wn);

    // epilogue: gelu(acc + b1) -> fp16 -> g_a2
    int n_base = n0 + wn * 64 + (lane & 3) * 2;
    int m_base = m0 + wm * 64 + (lane >> 2);
#pragma unroll
    for (int mt = 0; mt < 4; mt++) {
#pragma unroll
        for (int half = 0; half < 2; half++) {
            int m = m_base + mt * 16 + half * 8;
            if (m >= cnt) continue;
            __half* rowp = g_a2 + (size_t)(base + m) * FDIM;
#pragma unroll
            for (int j = 0; j < 8; j++) {
                int n = n_base + j * 8;
                float2 bv = *(const float2*)(b1 + e * FDIM + n);
                float g0 = gelu_exact(c[mt][j][half * 2 + 0] + bv.x);
                float g1 = gelu_exact(c[mt][j][half * 2 + 1] + bv.y);
                *(__half2*)(rowp + n) = __floats2half2_rn(g0, g1);
            }
        }
    }
}

__global__ void __launch_bounds__(256, 1)
gemm2_mma(const float* __restrict__ b2, float* __restrict__ out) {
    const int e = blockIdx.z;
    const int cnt = g_count[e];
    const int m0 = blockIdx.y * 128;
    if (m0 >= cnt) return;
    const int n0 = blockIdx.x * 256;
    const int base = g_offset[e];

    extern __shared__ char smb[];
    int tid = threadIdx.x, lane = tid & 31, wid = tid >> 5;
    int wm = wid & 1, wn = wid >> 1;

    const __half* Aseg = g_a2 + (size_t)(base + m0) * FDIM;
    const __half* Bseg = g_b2 + ((size_t)e * HDIM + n0) * FDIM;

    float c[4][8][4];
#pragma unroll
    for (int i = 0; i < 4; i++)
#pragma unroll
        for (int j = 0; j < 8; j++)
#pragma unroll
            for (int k = 0; k < 4; k++) c[i][j][k] = 0.f;

    mma_mainloop<FDIM>(Aseg, Bseg, smb, c, tid, lane, wm, wn);

    // epilogue: out[tok] += wt * (acc + b2)
    int n_base = n0 + wn * 64 + (lane & 3) * 2;
    int m_base = m0 + wm * 64 + (lane >> 2);
#pragma unroll
    for (int mt = 0; mt < 4; mt++) {
#pragma unroll
        for (int half = 0; half < 2; half++) {
            int m = m_base + mt * 16 + half * 8;
            if (m >= cnt) continue;
            int t = g_tok_slot[base + m];
            float wt = g_wt_slot[base + m];
            float* orow = out + (size_t)t * HDIM;
#pragma unroll
            for (int j = 0; j < 8; j++) {
                int n = n_base + j * 8;
                float2 bv = *(const float2*)(b2 + e * HDIM + n);
                atomicAdd(&orow[n],     wt * (c[mt][j][half * 2 + 0] + bv.x));
                atomicAdd(&orow[n + 1], wt * (c[mt][j][half * 2 + 1] + bv.y));
            }
        }
    }
}

// ---------------- launch ----------------
extern "C" void kernel_launch(void* const* d_in, const int* in_sizes, int n_in,
                              void* d_out, int out_size) {
    const float* x  = (const float*)d_in[0];
    const float* rw = (const float*)d_in[1];
    const float* rb = (const float*)d_in[2];
    const float* w1 = (const float*)d_in[3];
    const float* b1 = (const float*)d_in[4];
    const float* w2 = (const float*)d_in[5];
    const float* b2 = (const float*)d_in[6];
    float* out = (float*)d_out;

    cudaFuncSetAttribute(gemm1_mma, cudaFuncAttributeMaxDynamicSharedMemorySize, SMEM_DYN);
    cudaFuncSetAttribute(gemm2_mma, cudaFuncAttributeMaxDynamicSharedMemorySize, SMEM_DYN);

    cudaMemsetAsync(out, 0, (size_t)out_size * sizeof(float));
    zero_counts_kernel<<<1, 32>>>();
    router_kernel<<<TOK / 8, dim3(32, 8)>>>(x, rw, rb);
    prefix_kernel<<<1, 32>>>();
    scatter_kernel<<<TOK / 256, 256>>>();
    convx_kernel<<<NSLOT, 128>>>(x);
    convw_kernel<<<dim3(FDIM / 32, HDIM / 32, NEXP), dim3(32, 8)>>>(w1, 0, HDIM, FDIM);
    convw_kernel<<<dim3(HDIM / 32, FDIM / 32, NEXP), dim3(32, 8)>>>(w2, 1, FDIM, HDIM);

    gemm1_mma<<<dim3(FDIM / 256, TOK / 128, NEXP), 256, SMEM_DYN>>>(b1);
    gemm2_mma<<<dim3(HDIM / 256, TOK / 128, NEXP), 256, SMEM_DYN>>>(b2, out);
}